// round 5
// baseline (speedup 1.0000x reference)
#include <cuda_runtime.h>
#include <cuda_bf16.h>
#include <cstdint>

#define NN 100000
#define EE 1600000
#define IN_DIM 128
#define HH 64
#define GG 64
#define LN_EPS 1e-5f

// ---------------- device scratch ----------------
struct Hdr {
    int   cnt[NN];       // in-degree counts
    int   total;         // scan ticket
    float pool[2 * GG];  // sums[G], counts[G]
};
__device__ Hdr   g_h;
__device__ int   g_rowstart[NN];
__device__ int   g_cur[NN];
__device__ int   g_csrc[EE];
__device__ float g_bufA[(size_t)NN * HH];
__device__ float g_bufB[(size_t)NN * HH];
__device__ float g_s3[NN];

// ---------------- setup ----------------
__global__ void k_count(const int* __restrict__ dst) {
    int e = blockIdx.x * blockDim.x + threadIdx.x;
    if (e < EE) atomicAdd(&g_h.cnt[dst[e]], 1);
}

// single-kernel exclusive scan: per-block local scan + atomic ticket for base
__global__ void k_scan() {
    __shared__ int s[256];
    __shared__ int base;
    int tid = threadIdx.x;
    int i = blockIdx.x * 256 + tid;
    int c = (i < NN) ? g_h.cnt[i] : 0;
    s[tid] = c;
    __syncthreads();
    #pragma unroll
    for (int o = 1; o < 256; o <<= 1) {
        int v = (tid >= o) ? s[tid - o] : 0;
        __syncthreads();
        s[tid] += v;
        __syncthreads();
    }
    if (tid == 255) base = atomicAdd(&g_h.total, s[255]);
    __syncthreads();
    int excl = s[tid] - c + base;
    if (i < NN) { g_rowstart[i] = excl; g_cur[i] = excl; }
}

__global__ void k_fill(const int* __restrict__ src, const int* __restrict__ dst) {
    int e = blockIdx.x * blockDim.x + threadIdx.x;
    if (e < EE) {
        int d = dst[e];
        int pos = atomicAdd(&g_cur[d], 1);
        g_csrc[pos] = src[e];
    }
}

// ------- GEMM: Y[N][64] = rsqrt(cnt+1)[row] * (X[N][K] @ W[K][64]) -------
// 64x64 tile, 256 threads, thread = 4 rows x 4 cols.
// X tile stored TRANSPOSED in smem (XsT[k][row]) so the mainloop is
// 2x LDS.128 per 16 FMA instead of 4x LDS.32 + 1x LDS.128.
template <int K>
__global__ __launch_bounds__(256) void k_gemm(const float* __restrict__ X,
                                              const float* __restrict__ W,
                                              float* __restrict__ Y) {
    __shared__ float  XsT[64][68];    // [k][row], +4 pad
    __shared__ float4 Ws[64][16];
    const int tid  = threadIdx.x;
    const int row0 = blockIdx.x * 64;
    const int tx = tid & 15;          // col group (4 cols)
    const int ty = tid >> 4;          // row group (4 rows)

    float4 acc[4];
    #pragma unroll
    for (int r = 0; r < 4; r++) acc[r] = make_float4(0.f, 0.f, 0.f, 0.f);

    for (int kk = 0; kk < K; kk += 64) {
        #pragma unroll
        for (int i = tid; i < 1024; i += 256) {
            int k = i >> 4, c = i & 15;
            Ws[k][c] = reinterpret_cast<const float4*>(W)[(size_t)(kk + k) * 16 + c];
        }
        #pragma unroll
        for (int i = tid; i < 1024; i += 256) {
            int r = i >> 4, kv = i & 15;
            int row = row0 + r;
            float4 v = make_float4(0.f, 0.f, 0.f, 0.f);
            if (row < NN)
                v = reinterpret_cast<const float4*>(X)[(size_t)row * (K / 4) + (kk / 4) + kv];
            XsT[kv * 4 + 0][r] = v.x;
            XsT[kv * 4 + 1][r] = v.y;
            XsT[kv * 4 + 2][r] = v.z;
            XsT[kv * 4 + 3][r] = v.w;
        }
        __syncthreads();

        #pragma unroll 8
        for (int k = 0; k < 64; k++) {
            float4 xv = *reinterpret_cast<const float4*>(&XsT[k][ty * 4]); // broadcast
            float4 w  = Ws[k][tx];
            acc[0].x = fmaf(xv.x, w.x, acc[0].x);
            acc[0].y = fmaf(xv.x, w.y, acc[0].y);
            acc[0].z = fmaf(xv.x, w.z, acc[0].z);
            acc[0].w = fmaf(xv.x, w.w, acc[0].w);
            acc[1].x = fmaf(xv.y, w.x, acc[1].x);
            acc[1].y = fmaf(xv.y, w.y, acc[1].y);
            acc[1].z = fmaf(xv.y, w.z, acc[1].z);
            acc[1].w = fmaf(xv.y, w.w, acc[1].w);
            acc[2].x = fmaf(xv.z, w.x, acc[2].x);
            acc[2].y = fmaf(xv.z, w.y, acc[2].y);
            acc[2].z = fmaf(xv.z, w.z, acc[2].z);
            acc[2].w = fmaf(xv.z, w.w, acc[2].w);
            acc[3].x = fmaf(xv.w, w.x, acc[3].x);
            acc[3].y = fmaf(xv.w, w.y, acc[3].y);
            acc[3].z = fmaf(xv.w, w.z, acc[3].z);
            acc[3].w = fmaf(xv.w, w.w, acc[3].w);
        }
        __syncthreads();
    }

    #pragma unroll
    for (int r = 0; r < 4; r++) {
        int row = row0 + ty * 4 + r;
        if (row < NN) {
            float d = rsqrtf((float)g_h.cnt[row] + 1.0f);
            float4 a = acc[r];
            a.x *= d; a.y *= d; a.z *= d; a.w *= d;
            reinterpret_cast<float4*>(Y)[(size_t)row * 16 + tx] = a;
        }
    }
}

// ------- fused gather + self + di-postscale + bias + LN + ReLU (+ optional W3 dot) -------
template <bool FUSE_DOT>
__global__ __launch_bounds__(256) void k_agg_ln(const float* __restrict__ hs,
                                                float* __restrict__ Yout,
                                                const float* __restrict__ b,
                                                const float* __restrict__ gam,
                                                const float* __restrict__ bet,
                                                const float* __restrict__ W3) {
    int warp = (blockIdx.x * blockDim.x + threadIdx.x) >> 5;
    int lane = threadIdx.x & 31;
    if (warp >= NN) return;

    const int start = g_rowstart[warp];
    const int n     = g_h.cnt[warp];
    const float2* __restrict__ hp = reinterpret_cast<const float2*>(hs);

    float2 self = hp[(size_t)warp * 32 + lane];
    float a0 = self.x;
    float a1 = self.y;

    int j = 0;
    while (j + 32 <= n) {
        int idx = g_csrc[start + j + lane];
        #pragma unroll 8
        for (int t = 0; t < 32; t++) {
            int s = __shfl_sync(0xffffffffu, idx, t);
            float2 v = hp[(size_t)s * 32 + lane];
            a0 += v.x;
            a1 += v.y;
        }
        j += 32;
    }
    if (j < n) {
        int m = n - j;
        int idx = (j + lane < n) ? g_csrc[start + j + lane] : 0;
        #pragma unroll 4
        for (int t = 0; t < m; t++) {
            int s = __shfl_sync(0xffffffffu, idx, t);
            float2 v = hp[(size_t)s * 32 + lane];
            a0 += v.x;
            a1 += v.y;
        }
    }

    float dd = rsqrtf((float)n + 1.0f);
    float2 bv = reinterpret_cast<const float2*>(b)[lane];
    float x0 = fmaf(dd, a0, bv.x);
    float x1 = fmaf(dd, a1, bv.y);

    float s  = x0 + x1;
    float q  = x0 * x0 + x1 * x1;
    #pragma unroll
    for (int o = 16; o > 0; o >>= 1) {
        s += __shfl_xor_sync(0xffffffffu, s, o);
        q += __shfl_xor_sync(0xffffffffu, q, o);
    }
    float mu  = s * (1.0f / 64.0f);
    float var = q * (1.0f / 64.0f) - mu * mu;
    float rs  = rsqrtf(var + LN_EPS);
    float2 gv = reinterpret_cast<const float2*>(gam)[lane];
    float2 ev = reinterpret_cast<const float2*>(bet)[lane];
    float y0 = fmaxf(fmaf((x0 - mu) * rs, gv.x, ev.x), 0.0f);
    float y1 = fmaxf(fmaf((x1 - mu) * rs, gv.y, ev.y), 0.0f);

    if (FUSE_DOT) {
        float2 wv = reinterpret_cast<const float2*>(W3)[lane];
        float p = y0 * wv.x + y1 * wv.y;
        #pragma unroll
        for (int o = 16; o > 0; o >>= 1) p += __shfl_xor_sync(0xffffffffu, p, o);
        if (lane == 0) g_s3[warp] = p * dd;
    } else {
        float2 yv = make_float2(y0, y1);
        reinterpret_cast<float2*>(Yout)[(size_t)warp * 32 + lane] = yv;
    }
}

// layer-3 aggregation + node output + fused mean-pool accumulation
__global__ __launch_bounds__(256) void k_agg3(const float* __restrict__ b3,
                                              const int* __restrict__ batch,
                                              float* __restrict__ out) {
    __shared__ float ss[GG];
    __shared__ float sc[GG];
    int tid = threadIdx.x;
    if (tid < GG) { ss[tid] = 0.0f; sc[tid] = 0.0f; }
    __syncthreads();

    int warp = (blockIdx.x * blockDim.x + tid) >> 5;
    int lane = tid & 31;
    if (warp < NN) {
        int start = g_rowstart[warp];
        int n     = g_h.cnt[warp];
        float acc = 0.0f;
        for (int j = lane; j < n; j += 32)
            acc += g_s3[g_csrc[start + j]];
        #pragma unroll
        for (int o = 16; o > 0; o >>= 1) acc += __shfl_xor_sync(0xffffffffu, acc, o);
        if (lane == 0) {
            float dd = rsqrtf((float)n + 1.0f);
            float v = fmaf(dd, acc + g_s3[warp], b3[0]);
            out[warp] = v;
            int g = batch[warp];
            atomicAdd(&ss[g], v);
            atomicAdd(&sc[g], 1.0f);
        }
    }
    __syncthreads();
    if (tid < GG) {
        if (ss[tid] != 0.0f || sc[tid] != 0.0f) {
            atomicAdd(&g_h.pool[tid], ss[tid]);
            atomicAdd(&g_h.pool[GG + tid], sc[tid]);
        }
    }
}

__global__ void k_final(const float* __restrict__ Wg, const float* __restrict__ bg,
                        float* __restrict__ out) {
    int g = threadIdx.x;
    if (g < GG) {
        float s = g_h.pool[g];
        float c = g_h.pool[GG + g];
        float p = s / fmaxf(c, 1.0f);
        out[NN + g] = fmaf(p, Wg[0], bg[0]);
    }
}

// ---------------- launcher ----------------
extern "C" void kernel_launch(void* const* d_in, const int* in_sizes, int n_in,
                              void* d_out, int out_size) {
    const float* x    = (const float*)d_in[0];
    const int*   ei   = (const int*)d_in[1];
    const int*   batch= (const int*)d_in[2];
    const float* W1   = (const float*)d_in[3];
    const float* b1   = (const float*)d_in[4];
    const float* g1   = (const float*)d_in[5];
    const float* be1  = (const float*)d_in[6];
    const float* W2   = (const float*)d_in[7];
    const float* b2   = (const float*)d_in[8];
    const float* g2   = (const float*)d_in[9];
    const float* be2  = (const float*)d_in[10];
    const float* W3   = (const float*)d_in[11];
    const float* b3   = (const float*)d_in[12];
    const float* Wg   = (const float*)d_in[13];
    const float* bg   = (const float*)d_in[14];
    const int* src = ei;
    const int* dst = ei + EE;
    float* out = (float*)d_out;

    float *bufA, *bufB;
    void* hdrp;
    cudaGetSymbolAddress((void**)&bufA, g_bufA);
    cudaGetSymbolAddress((void**)&bufB, g_bufB);
    cudaGetSymbolAddress(&hdrp, g_h);

    static cudaStream_t s_side = nullptr;
    static cudaEvent_t  s_ev0  = nullptr;
    static cudaEvent_t  s_ev1  = nullptr;
    if (s_side == nullptr) {
        cudaStreamCreateWithFlags(&s_side, cudaStreamNonBlocking);
        cudaEventCreateWithFlags(&s_ev0, cudaEventDisableTiming);
        cudaEventCreateWithFlags(&s_ev1, cudaEventDisableTiming);
    }

    const int TB = 256;
    const int nblkN = (NN + TB - 1) / TB;      // 391
    const int nblkE = (EE + TB - 1) / TB;      // 6250
    const int nblkW = (NN * 32 + TB - 1) / TB; // 12500 warp-per-node
    const int nblkG = (NN + 63) / 64;          // 1563

    // zero counters + ticket + pool in one memset
    cudaMemsetAsync(hdrp, 0, sizeof(Hdr), 0);

    // degrees
    k_count<<<nblkE, TB>>>(dst);
    cudaEventRecord(s_ev0, 0);

    // side stream: CSR build (offsets + fill)
    cudaStreamWaitEvent(s_side, s_ev0, 0);
    k_scan<<<nblkN, 256, 0, s_side>>>();
    k_fill<<<nblkE, TB, 0, s_side>>>(src, dst);
    cudaEventRecord(s_ev1, s_side);

    // main stream: layer-1 GEMM concurrent with CSR build
    k_gemm<IN_DIM><<<nblkG, TB>>>(x, W1, bufA);
    cudaStreamWaitEvent(0, s_ev1, 0);

    // layer 1 aggregation + LN + ReLU
    k_agg_ln<false><<<nblkW, TB>>>(bufA, bufB, b1, g1, be1, nullptr);

    // layer 2 (W3 dot fused into epilogue)
    k_gemm<HH><<<nblkG, TB>>>(bufB, W2, bufA);
    k_agg_ln<true><<<nblkW, TB>>>(bufA, nullptr, b2, g2, be2, W3);

    // layer 3 aggregation + fused pooling
    k_agg3 <<<nblkW, TB>>>(b3, batch, out);
    k_final<<<1, 64>>>(Wg, bg, out);
}